// round 2
// baseline (speedup 1.0000x reference)
#include <cuda_runtime.h>
#include <math.h>

#define BN   64
#define PAST 128
#define FUT  64
#define NF   51
#define NO   50
#define NH   4
#define N1   (BN*PAST)   /* 8192 */
#define N2   (BN*FUT)    /* 4096 */
#define E1N  (N1*16)     /* 131072 */
#define E2N  (N2*16)     /* 65536 */
#define T1   (E1N+N1)
#define T2   (E2N+N2)
#define XB2  (N2/4)              /* 1024 blocks, 4 future nodes each */
#define HB   ((E1N+E2N)/256)     /* 768 hist blocks */

// ---------------- scratch ----------------
__device__ float d_y  [N1];            // x[:,50] (only column of x used later)
__device__ float d_x2 [N2*NO];         // only first 50 cols ever used
__device__ float d_h1 [N1*NH*NO];
__device__ float d_as1[N1*NH];
__device__ float d_ad1[N1*NH];
__device__ float d_x1o[N1*NO];
__device__ float d_M  [NO*NO];
__device__ float d_q1h[N1];
__device__ float d_z2 [N2*NO];
__device__ float d_h2 [N2*NH];
__device__ float d_as2[N2*NH];
__device__ float d_ad2[N2*NH];
__device__ int   d_cnt1[N1];           // zero at load; scan re-zeroes each call
__device__ int   d_off1[N1+1];
__device__ int   d_cur1[N1];
__device__ int   d_csr1[T1];
__device__ int   d_cnt2[N2];
__device__ int   d_off2[N2+1];
__device__ int   d_cur2[N2];
__device__ int   d_csr2[T2];

__device__ __forceinline__ float warp_max(float v) {
    #pragma unroll
    for (int o = 16; o; o >>= 1) v = fmaxf(v, __shfl_xor_sync(0xffffffffu, v, o));
    return v;
}
__device__ __forceinline__ float warp_sum(float v) {
    #pragma unroll
    for (int o = 16; o; o >>= 1) v += __shfl_xor_sync(0xffffffffu, v, o);
    return v;
}
__device__ __forceinline__ float lrelu(float x) { return x > 0.f ? x : 0.2f * x; }

// ================= Kernel A: pre+gemm1 | x2 pre | hist(both) | M =================
__global__ void kA(const int* __restrict__ cat1, const float* __restrict__ num1,
                   const int* __restrict__ cat2, const float* __restrict__ num2,
                   const int* __restrict__ e1,   const int* __restrict__ e2,
                   const float* __restrict__ e0w, const float* __restrict__ e1w,
                   const float* __restrict__ e2w,
                   const float* __restrict__ lin, const float* __restrict__ asrc,
                   const float* __restrict__ adst, const float* __restrict__ W) {
    int bb = blockIdx.x;
    int t  = threadIdx.x;

    if (bb < N1) {
        // ---- preprocess node bb + GAT1 linear + attention scalars ----
        __shared__ float xs[NF];
        __shared__ float hs[NH*NO];
        if (t < NF) {
            float v;
            if      (t < 16) v = e0w[cat1[bb*3+0]*16 + t];
            else if (t < 24) v = e1w[cat1[bb*3+1]*8  + (t-16)];
            else if (t < 48) v = e2w[cat1[bb*3+2]*24 + (t-24)];
            else             v = num1[bb*3 + (t-48)];
            xs[t] = v;
            if (t == NF-1) d_y[bb] = v;
        }
        __syncthreads();
        if (t < NH*NO) {
            float acc = 0.f;
            #pragma unroll
            for (int k = 0; k < NF; k++) acc += xs[k] * lin[k*(NH*NO) + t];
            hs[t] = acc;
            d_h1[bb*(NH*NO) + t] = acc;
        }
        __syncthreads();
        if (t < 8) {
            int head = t & 3;
            const float* att = (t < 4) ? asrc : adst;
            float a = 0.f;
            #pragma unroll
            for (int c = 0; c < NO; c++) a += hs[head*NO + c] * att[head*NO + c];
            if (t < 4) d_as1[bb*NH + head] = a;
            else       d_ad1[bb*NH + head] = a;
        }
        return;
    }
    bb -= N1;
    if (bb < XB2) {
        // ---- preprocess 4 future nodes (only cols 0..49 needed) ----
        int sub = t >> 6, c = t & 63;
        int n = bb*4 + sub;
        if (c < NO) {
            float v;
            if      (c < 16) v = e0w[cat2[n*3+0]*16 + c];
            else if (c < 24) v = e1w[cat2[n*3+1]*8  + (c-16)];
            else if (c < 48) v = e2w[cat2[n*3+2]*24 + (c-24)];
            else             v = num2[n*3 + (c-48)];
            d_x2[n*NO + c] = v;
        }
        return;
    }
    bb -= XB2;
    if (bb < HB) {
        // ---- histogram of dst for both graphs ----
        int i = bb*256 + t;
        if (i < E1N) atomicAdd(&d_cnt1[e1[E1N + i]], 1);
        else         atomicAdd(&d_cnt2[e2[E2N + (i - E1N)]], 1);
        return;
    }
    // ---- last block: M = 2 * W @ W^T ----
    for (int idx = t; idx < NO*NO; idx += blockDim.x) {
        int i = idx / NO, j = idx % NO;
        float s = 0.f;
        #pragma unroll
        for (int k = 0; k < 64; k++) s += W[i*64+k] * W[j*64+k];
        d_M[idx] = 2.f * s;
    }
}

// ================= Kernel B: scan (block0=g1, block1=g2), self-restoring cnt =====
__global__ void kScan() {
    int g = blockIdx.x;
    const int n = g ? N2 : N1;
    int* cnt = g ? d_cnt2 : d_cnt1;
    int* off = g ? d_off2 : d_off1;
    int* cur = g ? d_cur2 : d_cur1;
    int* csr = g ? d_csr2 : d_csr1;
    __shared__ int part[1024];
    int t = threadIdx.x;
    int chunk = n >> 10;           // 8 or 4
    int start = t * chunk;
    int local[8];
    int s = 0;
    for (int i = 0; i < chunk; i++) {
        local[i] = cnt[start + i] + 1;   // +1 self loop
        cnt[start + i] = 0;              // restore for next replay
        s += local[i];
    }
    part[t] = s;
    __syncthreads();
    for (int d = 1; d < 1024; d <<= 1) {
        int v = (t >= d) ? part[t-d] : 0;
        __syncthreads();
        part[t] += v;
        __syncthreads();
    }
    int run = (t == 0) ? 0 : part[t-1];
    for (int i = 0; i < chunk; i++) {
        off[start+i] = run;
        csr[run]     = start + i;        // self loop in slot 0
        cur[start+i] = run + 1;
        run += local[i];
    }
    if (t == 1023) off[n] = run;
}

// ================= Kernel C: scatter (both graphs) ===============================
__global__ void kScatter(const int* __restrict__ e1, const int* __restrict__ e2) {
    int i = blockIdx.x*256 + threadIdx.x;
    if (i < E1N) {
        int s = e1[i], d = e1[E1N + i];
        d_csr1[atomicAdd(&d_cur1[d], 1)] = s;
    } else {
        int j = i - E1N;
        int s = e2[j], d = e2[E2N + j];
        d_csr2[atomicAdd(&d_cur2[d], 1)] = s;
    }
}

// ============ Kernel D: GAT1 aggregate + quad (past) | z2 = M x2 (future) ========
__global__ void kAgg1(const float* __restrict__ bias) {
    int n = blockIdx.x;
    int t = threadIdx.x;
    if (n >= N1) {
        int m = n - N1;
        __shared__ float xs[NO];
        if (t < NO) xs[t] = d_x2[m*NO + t];
        __syncthreads();
        if (t < NO) {
            float z = 0.f;
            #pragma unroll
            for (int j = 0; j < NO; j++) z += d_M[t*NO + j] * xs[j];
            d_z2[m*NO + t] = z;
        }
        return;
    }
    int w = t >> 5, lane = t & 31;
    int beg = d_off1[n], end = d_off1[n+1];
    float adst = d_ad1[n*NH + w];

    float mx = -1e30f;
    for (int i = beg + lane; i < end; i += 32) {
        int s = d_csr1[i];
        mx = fmaxf(mx, lrelu(d_as1[s*NH + w] + adst));
    }
    mx = warp_max(mx);

    float acc0 = 0.f, acc1 = 0.f, ssum = 0.f;
    int c0 = lane, c1 = lane + 32;
    for (int i = beg; i < end; i++) {
        int s = d_csr1[i];
        float ex = expf(lrelu(d_as1[s*NH + w] + adst) - mx);
        ssum += ex;
        const float* hr = &d_h1[s*(NH*NO) + w*NO];
        acc0 += ex * hr[c0];
        if (c1 < NO) acc1 += ex * hr[c1];
    }
    float inv = 0.25f / (ssum + 1e-16f);

    __shared__ float so[NO];
    __shared__ float red[128];
    if (t < NO) so[t] = 0.f;
    __syncthreads();
    atomicAdd(&so[c0], acc0 * inv);
    if (c1 < NO) atomicAdd(&so[c1], acc1 * inv);
    __syncthreads();
    if (t < NO) {
        float v = so[t] + bias[t];
        so[t] = v;
        d_x1o[n*NO + t] = v;
    }
    __syncthreads();
    // quad: -0.5 * x1^T M x1
    float p = 0.f;
    if (t < NO) {
        float mi = 0.f;
        #pragma unroll
        for (int j = 0; j < NO; j++) mi += d_M[t*NO + j] * so[j];
        p = mi * so[t];
    }
    red[t] = p;
    __syncthreads();
    for (int s = 64; s; s >>= 1) { if (t < s) red[t] += red[t+s]; __syncthreads(); }
    if (t == 0) d_q1h[n] = -0.5f * red[0];
}

// ============ Kernel E: attention softmax + GAT2 linear (fused per future node) ==
__global__ void kAttn(const int* __restrict__ A, const float* __restrict__ lin,
                      const float* __restrict__ asrc, const float* __restrict__ adst) {
    int n = blockIdx.x;           // b*64 + f
    int b = n >> 6, f = n & 63;
    int t = threadIdx.x;          // p in [0,128)
    __shared__ float zs[NO];
    __shared__ float red[128];
    __shared__ float s_tmp;
    if (t < NO) zs[t] = d_z2[n*NO + t];
    __syncthreads();
    int node = b*PAST + t;
    float dot = 0.f;
    #pragma unroll
    for (int c = 0; c < NO; c++) dot += zs[c] * d_x1o[node*NO + c];
    float logit = d_q1h[node] + dot;
    if (A[t*(PAST+FUT) + PAST + f] == 0) logit = -INFINITY;

    red[t] = logit;
    __syncthreads();
    for (int s = 64; s; s >>= 1) { if (t < s) red[t] = fmaxf(red[t], red[t+s]); __syncthreads(); }
    float mx = red[0];
    __syncthreads();
    float ex = (logit == -INFINITY) ? 0.f : expf(logit - mx);
    red[t] = ex;
    __syncthreads();
    for (int s = 64; s; s >>= 1) { if (t < s) red[t] += red[t+s]; __syncthreads(); }
    float ssum = red[0];
    __syncthreads();
    red[t] = ex * d_y[node];
    __syncthreads();
    for (int s = 64; s; s >>= 1) { if (t < s) red[t] += red[t+s]; __syncthreads(); }
    if (t == 0) s_tmp = red[0] / ssum;
    __syncthreads();

    // GAT2 linear for node n (warp 0)
    if (t < 32) {
        int h = t & 3;
        float acc = 0.f;
        for (int k = (t >> 2); k < NO; k += 8) acc += d_x2[n*NO + k] * lin[k*NH + h];
        acc += __shfl_xor_sync(0xffffffffu, acc, 4);
        acc += __shfl_xor_sync(0xffffffffu, acc, 8);
        acc += __shfl_xor_sync(0xffffffffu, acc, 16);
        if (t < NH) {
            float v = acc + s_tmp * lin[NO*NH + h];
            d_h2[n*NH + h]  = v;
            d_as2[n*NH + h] = v * asrc[h];
            d_ad2[n*NH + h] = v * adst[h];
        }
    }
}

// ================= Kernel F: GAT2 aggregate =====================================
__global__ void kAgg2(const float* __restrict__ bias, float* __restrict__ out) {
    int n = blockIdx.x*4 + (threadIdx.x >> 5);
    int lane = threadIdx.x & 31;
    if (n >= N2) return;
    int beg = d_off2[n], end = d_off2[n+1];
    float total = 0.f;
    #pragma unroll
    for (int h = 0; h < NH; h++) {
        float adst = d_ad2[n*NH + h];
        float mx = -1e30f;
        for (int i = beg + lane; i < end; i += 32) {
            int s = d_csr2[i];
            mx = fmaxf(mx, lrelu(d_as2[s*NH + h] + adst));
        }
        mx = warp_max(mx);
        float ssum = 0.f, wsum = 0.f;
        for (int i = beg + lane; i < end; i += 32) {
            int s = d_csr2[i];
            float ex = expf(lrelu(d_as2[s*NH + h] + adst) - mx);
            ssum += ex;
            wsum += ex * d_h2[s*NH + h];
        }
        ssum = warp_sum(ssum);
        wsum = warp_sum(wsum);
        total += 0.25f * wsum / (ssum + 1e-16f);
    }
    if (lane == 0) out[n] = total + bias[0];
}

// ================= launch =================
extern "C" void kernel_launch(void* const* d_in, const int* in_sizes, int n_in,
                              void* d_out, int out_size) {
    const int*   cat1   = (const int*)  d_in[0];
    const float* num1   = (const float*)d_in[1];
    const int*   cat2   = (const int*)  d_in[2];
    const float* num2   = (const float*)d_in[3];
    const int*   e1     = (const int*)  d_in[4];
    const int*   e2     = (const int*)  d_in[5];
    const int*   A      = (const int*)  d_in[6];
    const float* emb0   = (const float*)d_in[7];
    const float* emb1   = (const float*)d_in[8];
    const float* emb2   = (const float*)d_in[9];
    const float* g1_lin = (const float*)d_in[10];
    const float* g1_as  = (const float*)d_in[11];
    const float* g1_ad  = (const float*)d_in[12];
    const float* g1_b   = (const float*)d_in[13];
    const float* g2_lin = (const float*)d_in[14];
    const float* g2_as  = (const float*)d_in[15];
    const float* g2_ad  = (const float*)d_in[16];
    const float* g2_b   = (const float*)d_in[17];
    const float* W      = (const float*)d_in[18];
    float* out = (float*)d_out;

    kA<<<N1 + XB2 + HB + 1, 256>>>(cat1, num1, cat2, num2, e1, e2,
                                   emb0, emb1, emb2, g1_lin, g1_as, g1_ad, W);
    kScan<<<2, 1024>>>();
    kScatter<<<HB, 256>>>(e1, e2);
    kAgg1<<<N1 + N2, 128>>>(g1_b);
    kAttn<<<N2, 128>>>(A, g2_lin, g2_as, g2_ad);
    kAgg2<<<(N2+3)/4, 128>>>(g2_b, out);
}

// round 3
// speedup vs baseline: 1.1690x; 1.1690x over previous
#include <cuda_runtime.h>
#include <math.h>

#define BN   64
#define PAST 128
#define FUT  64
#define NF   51
#define NO   50
#define NH   4
#define N1   (BN*PAST)   /* 8192 */
#define N2   (BN*FUT)    /* 4096 */
#define E1N  (N1*16)
#define E2N  (N2*16)
#define T1   (E1N+N1)
#define T2   (E2N+N2)
#define G1B  (N1/16)             /* 512 gemm blocks, 16 nodes each */
#define XB2  (N2/4)              /* 1024 x2-pre blocks */
#define HB   ((E1N+E2N)/256)     /* 768 hist blocks */
#define Z2PB 20
#define Z2B  ((N2+Z2PB-1)/Z2PB)  /* 205 */

// ---------------- scratch ----------------
__device__ float d_y  [N1];
__device__ float d_x2 [N2*NO];
__device__ float d_h1 [N1*NH*NO];
__device__ float d_as1[N1*NH];
__device__ float d_ad1[N1*NH];
__device__ float d_x1o[N1*NO];
__device__ float d_M  [NO*NO];
__device__ float d_q1h[N1];
__device__ float d_z2 [N2*NO];
__device__ float d_h2 [N2*NH];
__device__ float d_as2[N2*NH];
__device__ float d_ad2[N2*NH];
__device__ unsigned d_maskw[FUT*4];
__device__ int   d_cnt1[N1];
__device__ int   d_off1[N1+1];
__device__ int   d_cur1[N1];
__device__ int   d_csr1[T1];
__device__ int   d_cnt2[N2];
__device__ int   d_off2[N2+1];
__device__ int   d_cur2[N2];
__device__ int   d_csr2[T2];

__device__ __forceinline__ float warp_sum(float v) {
    #pragma unroll
    for (int o = 16; o; o >>= 1) v += __shfl_xor_sync(0xffffffffu, v, o);
    return v;
}
__device__ __forceinline__ float lrelu(float x) { return x > 0.f ? x : 0.2f * x; }

// ================= Kernel A =================
__global__ void kA(const int* __restrict__ cat1, const float* __restrict__ num1,
                   const int* __restrict__ cat2, const float* __restrict__ num2,
                   const int* __restrict__ e1,   const int* __restrict__ e2,
                   const int* __restrict__ A,
                   const float* __restrict__ e0w, const float* __restrict__ e1w,
                   const float* __restrict__ e2w,
                   const float* __restrict__ lin, const float* __restrict__ asrc,
                   const float* __restrict__ adst, const float* __restrict__ W) {
    int bb = blockIdx.x;
    int t  = threadIdx.x;

    if (bb < G1B) {
        // ---- GAT1 linear for 16 past nodes, lin column per thread ----
        __shared__ float xs[16*NF];
        __shared__ float hs[16*NH*NO];
        int n0 = bb*16;
        for (int idx = t; idx < 16*NF; idx += 256) {
            int j = idx / NF, k = idx % NF, n = n0 + j;
            float v;
            if      (k < 16) v = e0w[cat1[n*3+0]*16 + k];
            else if (k < 24) v = e1w[cat1[n*3+1]*8  + (k-16)];
            else if (k < 48) v = e2w[cat1[n*3+2]*24 + (k-24)];
            else             v = num1[n*3 + (k-48)];
            xs[idx] = v;
            if (k == NF-1) d_y[n] = v;
        }
        __syncthreads();
        if (t < NH*NO) {
            float acc[16];
            #pragma unroll
            for (int j = 0; j < 16; j++) acc[j] = 0.f;
            for (int k = 0; k < NF; k++) {
                float l = __ldg(&lin[k*(NH*NO) + t]);
                #pragma unroll
                for (int j = 0; j < 16; j++) acc[j] += xs[j*NF + k] * l;
            }
            #pragma unroll
            for (int j = 0; j < 16; j++) {
                d_h1[(n0+j)*(NH*NO) + t] = acc[j];
                hs[j*(NH*NO) + t] = acc[j];
            }
        }
        __syncthreads();
        if (t < 128) {
            int j = t >> 3, r = t & 7, head = r & 3;
            const float* att = (r < 4) ? asrc : adst;
            float a = 0.f;
            #pragma unroll
            for (int c = 0; c < NO; c++)
                a += hs[j*(NH*NO) + head*NO + c] * att[head*NO + c];
            if (r < 4) d_as1[(n0+j)*NH + head] = a;
            else       d_ad1[(n0+j)*NH + head] = a;
        }
        return;
    }
    bb -= G1B;
    if (bb < XB2) {
        int sub = t >> 6, c = t & 63;
        int n = bb*4 + sub;
        if (c < NO) {
            float v;
            if      (c < 16) v = e0w[cat2[n*3+0]*16 + c];
            else if (c < 24) v = e1w[cat2[n*3+1]*8  + (c-16)];
            else if (c < 48) v = e2w[cat2[n*3+2]*24 + (c-24)];
            else             v = num2[n*3 + (c-48)];
            d_x2[n*NO + c] = v;
        }
        return;
    }
    bb -= XB2;
    if (bb < HB) {
        int i = bb*256 + t;
        if (i < E1N) atomicAdd(&d_cnt1[e1[E1N + i]], 1);
        else         atomicAdd(&d_cnt2[e2[E2N + (i - E1N)]], 1);
        return;
    }
    bb -= HB;
    if (bb == 0) {
        // M = 2 W W^T
        for (int idx = t; idx < NO*NO; idx += 256) {
            int i = idx / NO, j = idx % NO;
            float s = 0.f;
            #pragma unroll
            for (int k = 0; k < 64; k++) s += W[i*64+k] * W[j*64+k];
            d_M[idx] = 2.f * s;
        }
        return;
    }
    // mask bit-pack: maskw[f][wd] bit i = A[(wd*32+i)*192 + 128 + f]
    if (t < FUT*4) {
        int f = t >> 2, wd = t & 3;
        unsigned u = 0;
        for (int i = 0; i < 32; i++)
            if (A[(wd*32+i)*(PAST+FUT) + PAST + f]) u |= (1u << i);
        d_maskw[f*4 + wd] = u;
    }
}

// ================= Kernel B: scan (blocks 0,1) + z2 (rest) =================
template<int CHUNK, int NN>
__device__ __forceinline__ void scan_t(int* cnt, int* off, int* cur, int* csr, int* part) {
    int t = threadIdx.x;
    int start = t * CHUNK;
    int local[CHUNK];
    int s = 0;
    #pragma unroll
    for (int i = 0; i < CHUNK; i++) {
        local[i] = cnt[start+i] + 1;   // + self loop
        cnt[start+i] = 0;              // restore for next replay
        s += local[i];
    }
    part[t] = s;
    __syncthreads();
    for (int d = 1; d < 1024; d <<= 1) {
        int v = (t >= d) ? part[t-d] : 0;
        __syncthreads();
        part[t] += v;
        __syncthreads();
    }
    int run = (t == 0) ? 0 : part[t-1];
    #pragma unroll
    for (int i = 0; i < CHUNK; i++) {
        off[start+i] = run;
        csr[run]     = start + i;      // self loop slot 0
        cur[start+i] = run + 1;
        run += local[i];
    }
    if (t == 1023) off[NN] = run;
}

__global__ void kScanZ2() {
    __shared__ float sm[NO*NO + Z2PB*NO];   // 14 KB, reused as int for scan
    int b = blockIdx.x, t = threadIdx.x;
    if (b == 0) { scan_t<8, N1>(d_cnt1, d_off1, d_cur1, d_csr1, (int*)sm); return; }
    if (b == 1) { scan_t<4, N2>(d_cnt2, d_off2, d_cur2, d_csr2, (int*)sm); return; }
    // z2 = M @ x2 for 20 nodes
    int base = (b - 2) * Z2PB;
    float* Ms  = sm;
    float* x2s = sm + NO*NO;
    for (int idx = t; idx < NO*NO; idx += 1024) Ms[idx] = d_M[idx];
    for (int idx = t; idx < Z2PB*NO; idx += 1024) {
        int gl = base*NO + idx;
        x2s[idx] = (gl < N2*NO) ? d_x2[gl] : 0.f;
    }
    __syncthreads();
    if (t < Z2PB*NO) {
        int ln = t / NO, c = t % NO;
        int node = base + ln;
        if (node < N2) {
            float z = 0.f;
            #pragma unroll
            for (int j = 0; j < NO; j++) z += Ms[c*NO + j] * x2s[ln*NO + j];
            d_z2[node*NO + c] = z;
        }
    }
}

// ================= Kernel C: scatter =================
__global__ void kScatter(const int* __restrict__ e1, const int* __restrict__ e2) {
    int i = blockIdx.x*256 + threadIdx.x;
    if (i < E1N) {
        int s = e1[i], d = e1[E1N + i];
        d_csr1[atomicAdd(&d_cur1[d], 1)] = s;
    } else {
        int j = i - E1N;
        int s = e2[j], d = e2[E2N + j];
        d_csr2[atomicAdd(&d_cur2[d], 1)] = s;
    }
}

// ============ Kernel D: GAT1 aggregate + quad (no max pass) ============
__global__ void kAgg1(const float* __restrict__ bias) {
    int n = blockIdx.x, t = threadIdx.x;
    int w = t >> 5, lane = t & 31;
    int beg = d_off1[n], end = d_off1[n+1];
    float adst = d_ad1[n*NH + w];

    float ssum = 0.f, a0 = 0.f, a1 = 0.f, b0 = 0.f, b1 = 0.f;
    int c0 = lane, c1 = lane + 32;
    bool has1 = (c1 < NO);
    int i = beg;
    for (; i + 2 <= end; i += 2) {
        int s0 = d_csr1[i], s1 = d_csr1[i+1];
        float e0 = expf(lrelu(__ldg(&d_as1[s0*NH + w]) + adst));
        float e1 = expf(lrelu(__ldg(&d_as1[s1*NH + w]) + adst));
        ssum += e0 + e1;
        const float* h0 = &d_h1[s0*(NH*NO) + w*NO];
        const float* h1 = &d_h1[s1*(NH*NO) + w*NO];
        a0 += e0 * h0[c0];
        b0 += e1 * h1[c0];
        if (has1) { a1 += e0 * h0[c1]; b1 += e1 * h1[c1]; }
    }
    if (i < end) {
        int s0 = d_csr1[i];
        float e0 = expf(lrelu(__ldg(&d_as1[s0*NH + w]) + adst));
        ssum += e0;
        const float* h0 = &d_h1[s0*(NH*NO) + w*NO];
        a0 += e0 * h0[c0];
        if (has1) a1 += e0 * h0[c1];
    }
    a0 += b0; a1 += b1;
    float inv = 0.25f / (ssum + 1e-16f);

    __shared__ float so[NO];
    __shared__ float red[128];
    if (t < NO) so[t] = 0.f;
    __syncthreads();
    atomicAdd(&so[c0], a0 * inv);
    if (has1) atomicAdd(&so[c1], a1 * inv);
    __syncthreads();
    if (t < NO) {
        float v = so[t] + bias[t];
        so[t] = v;
        d_x1o[n*NO + t] = v;
    }
    __syncthreads();
    // quad: -0.5 x1^T M x1, coalesced linear sweep of M
    float p = 0.f;
    for (int idx = t; idx < NO*NO; idx += 128)
        p += __ldg(&d_M[idx]) * so[idx/NO] * so[idx%NO];
    red[t] = p;
    __syncthreads();
    if (t < 64) red[t] += red[t+64];
    __syncthreads();
    if (t < 32) {
        float v = red[t] + red[t+32];
        v = warp_sum(v);
        if (t == 0) d_q1h[n] = -0.5f * v;
    }
}

// ============ Kernel E: attention + GAT2 linear ============
__global__ void kAttn(const float* __restrict__ lin,
                      const float* __restrict__ asrc, const float* __restrict__ adst) {
    int n = blockIdx.x;           // b*64 + f
    int b = n >> 6, f = n & 63;
    int t = threadIdx.x;          // p
    __shared__ float zs[NO];
    __shared__ float xt[PAST*(NO+1)];
    __shared__ float rs[4], rw[4];
    __shared__ float s_tmp;
    if (t < NO) zs[t] = d_z2[n*NO + t];
    {   // stage x1o tile coalesced, padded rows
        const float* src = &d_x1o[(size_t)b*PAST*NO];
        for (int idx = t; idx < PAST*NO; idx += 128) {
            int row = idx / NO, c = idx % NO;
            xt[row*(NO+1) + c] = src[idx];
        }
    }
    __syncthreads();
    int node = b*PAST + t;
    float dot = 0.f;
    #pragma unroll
    for (int c = 0; c < NO; c++) dot += zs[c] * xt[t*(NO+1) + c];
    float logit = d_q1h[node] + dot;
    unsigned mk = (d_maskw[f*4 + (t>>5)] >> (t & 31)) & 1u;
    float ex = mk ? expf(logit) : 0.f;
    float wv = ex * d_y[node];

    float s1 = warp_sum(ex);
    float w1 = warp_sum(wv);
    if ((t & 31) == 0) { rs[t>>5] = s1; rw[t>>5] = w1; }
    __syncthreads();
    if (t == 0) {
        float S = rs[0]+rs[1]+rs[2]+rs[3];
        float Wv = rw[0]+rw[1]+rw[2]+rw[3];
        s_tmp = Wv / (S + 1e-16f);
    }
    __syncthreads();

    if (t < 32) {
        int h = t & 3;
        float acc = 0.f;
        for (int k = (t >> 2); k < NO; k += 8) acc += d_x2[n*NO + k] * lin[k*NH + h];
        acc += __shfl_xor_sync(0xffffffffu, acc, 4);
        acc += __shfl_xor_sync(0xffffffffu, acc, 8);
        acc += __shfl_xor_sync(0xffffffffu, acc, 16);
        if (t < NH) {
            float v = acc + s_tmp * lin[NO*NH + h];
            d_h2[n*NH + h]  = v;
            d_as2[n*NH + h] = v * asrc[h];
            d_ad2[n*NH + h] = v * adst[h];
        }
    }
}

// ================= Kernel F: GAT2 aggregate (no max) =================
__global__ void kAgg2(const float* __restrict__ bias, float* __restrict__ out) {
    int n = blockIdx.x*4 + (threadIdx.x >> 5);
    int lane = threadIdx.x & 31;
    int beg = d_off2[n], end = d_off2[n+1];
    float4 ad = *(const float4*)&d_ad2[n*NH];
    float ss0=0,ss1=0,ss2=0,ss3=0, ws0=0,ws1=0,ws2=0,ws3=0;
    for (int i = beg + lane; i < end; i += 32) {
        int s = d_csr2[i];
        float4 av = *(const float4*)&d_as2[s*NH];
        float4 hv = *(const float4*)&d_h2[s*NH];
        float e0 = expf(lrelu(av.x + ad.x));
        float e1 = expf(lrelu(av.y + ad.y));
        float e2 = expf(lrelu(av.z + ad.z));
        float e3 = expf(lrelu(av.w + ad.w));
        ss0+=e0; ws0+=e0*hv.x;
        ss1+=e1; ws1+=e1*hv.y;
        ss2+=e2; ws2+=e2*hv.z;
        ss3+=e3; ws3+=e3*hv.w;
    }
    ss0=warp_sum(ss0); ws0=warp_sum(ws0);
    ss1=warp_sum(ss1); ws1=warp_sum(ws1);
    ss2=warp_sum(ss2); ws2=warp_sum(ws2);
    ss3=warp_sum(ss3); ws3=warp_sum(ws3);
    if (lane == 0) {
        float total = 0.25f*ws0/(ss0+1e-16f) + 0.25f*ws1/(ss1+1e-16f)
                    + 0.25f*ws2/(ss2+1e-16f) + 0.25f*ws3/(ss3+1e-16f);
        out[n] = total + bias[0];
    }
}

// ================= launch =================
extern "C" void kernel_launch(void* const* d_in, const int* in_sizes, int n_in,
                              void* d_out, int out_size) {
    const int*   cat1   = (const int*)  d_in[0];
    const float* num1   = (const float*)d_in[1];
    const int*   cat2   = (const int*)  d_in[2];
    const float* num2   = (const float*)d_in[3];
    const int*   e1     = (const int*)  d_in[4];
    const int*   e2     = (const int*)  d_in[5];
    const int*   A      = (const int*)  d_in[6];
    const float* emb0   = (const float*)d_in[7];
    const float* emb1   = (const float*)d_in[8];
    const float* emb2   = (const float*)d_in[9];
    const float* g1_lin = (const float*)d_in[10];
    const float* g1_as  = (const float*)d_in[11];
    const float* g1_ad  = (const float*)d_in[12];
    const float* g1_b   = (const float*)d_in[13];
    const float* g2_lin = (const float*)d_in[14];
    const float* g2_as  = (const float*)d_in[15];
    const float* g2_ad  = (const float*)d_in[16];
    const float* g2_b   = (const float*)d_in[17];
    const float* W      = (const float*)d_in[18];
    float* out = (float*)d_out;

    kA<<<G1B + XB2 + HB + 2, 256>>>(cat1, num1, cat2, num2, e1, e2, A,
                                    emb0, emb1, emb2, g1_lin, g1_as, g1_ad, W);
    kScanZ2<<<2 + Z2B, 1024>>>();
    kScatter<<<HB, 256>>>(e1, e2);
    kAgg1<<<N1, 128>>>(g1_b);
    kAttn<<<N2, 128>>>(g2_lin, g2_as, g2_ad);
    kAgg2<<<N2/4, 128>>>(g2_b, out);
}

// round 4
// speedup vs baseline: 1.3914x; 1.1902x over previous
#include <cuda_runtime.h>
#include <math.h>

#define BN   64
#define PAST 128
#define FUT  64
#define NF   51
#define NO   50
#define NH   4
#define N1   (BN*PAST)   /* 8192 */
#define N2   (BN*FUT)    /* 4096 */
#define E1N  (N1*16)
#define E2N  (N2*16)
#define T1   (E1N+N1)    /* 139264 */
#define T2   (E2N+N2)    /* 69632 */
#define G1B  (N1/16)             /* 512 */
#define XB2  (N2/4)              /* 1024 */
#define HB   ((E1N+E2N)/256)     /* 768 */
#define Z2PB 20
#define Z2B  ((N2+Z2PB-1)/Z2PB)  /* 205 */
#define SCB  ((T1+T2+255)/256)   /* 816 scatter blocks */

// ---------------- scratch ----------------
__device__ float d_y  [N1];
__device__ float d_x2 [N2*NO];
__device__ float d_h1 [N1*NH*NO];
__device__ __align__(16) float d_as1[N1*NH];
__device__ __align__(16) float d_ad1[N1*NH];
__device__ float d_x1o[N1*NO];
__device__ float d_M  [NO*NO];
__device__ float d_q1h[N1];
__device__ float d_z2 [N2*NO];
__device__ __align__(16) float d_h2 [N2*NH];
__device__ __align__(16) float d_as2[N2*NH];
__device__ __align__(16) float d_ad2[N2*NH];
__device__ float d_ew1[NH*T1];         // head-major edge weights, graph1
__device__ unsigned d_maskw[FUT*4];
__device__ int   d_cnt1[N1];
__device__ int   d_off1[N1+1];
__device__ int   d_cur1[N1];
__device__ int   d_csr1[T1];
__device__ int   d_cnt2[N2];
__device__ int   d_off2[N2+1];
__device__ int   d_cur2[N2];
__device__ int   d_csr2[T2];

__device__ __forceinline__ float warp_sum(float v) {
    #pragma unroll
    for (int o = 16; o; o >>= 1) v += __shfl_xor_sync(0xffffffffu, v, o);
    return v;
}
__device__ __forceinline__ float lrelu(float x) { return x > 0.f ? x : 0.2f * x; }

// ================= Kernel A: gemm1 | x2-pre | hist | M | mask =================
__global__ void kA(const int* __restrict__ cat1, const float* __restrict__ num1,
                   const int* __restrict__ cat2, const float* __restrict__ num2,
                   const int* __restrict__ e1,   const int* __restrict__ e2,
                   const int* __restrict__ A,
                   const float* __restrict__ e0w, const float* __restrict__ e1w,
                   const float* __restrict__ e2w,
                   const float* __restrict__ lin, const float* __restrict__ asrc,
                   const float* __restrict__ adst, const float* __restrict__ W) {
    int bb = blockIdx.x;
    int t  = threadIdx.x;

    if (bb < G1B) {
        __shared__ float xs[16*NF];
        __shared__ float hs[16*NH*NO];
        int n0 = bb*16;
        for (int idx = t; idx < 16*NF; idx += 256) {
            int j = idx / NF, k = idx % NF, n = n0 + j;
            float v;
            if      (k < 16) v = e0w[cat1[n*3+0]*16 + k];
            else if (k < 24) v = e1w[cat1[n*3+1]*8  + (k-16)];
            else if (k < 48) v = e2w[cat1[n*3+2]*24 + (k-24)];
            else             v = num1[n*3 + (k-48)];
            xs[idx] = v;
            if (k == NF-1) d_y[n] = v;
        }
        __syncthreads();
        if (t < NH*NO) {
            float acc[16];
            #pragma unroll
            for (int j = 0; j < 16; j++) acc[j] = 0.f;
            for (int k = 0; k < NF; k++) {
                float l = __ldg(&lin[k*(NH*NO) + t]);
                #pragma unroll
                for (int j = 0; j < 16; j++) acc[j] += xs[j*NF + k] * l;
            }
            #pragma unroll
            for (int j = 0; j < 16; j++) {
                d_h1[(n0+j)*(NH*NO) + t] = acc[j];
                hs[j*(NH*NO) + t] = acc[j];
            }
        }
        __syncthreads();
        if (t < 128) {
            int j = t >> 3, r = t & 7, head = r & 3;
            const float* att = (r < 4) ? asrc : adst;
            float a = 0.f;
            #pragma unroll
            for (int c = 0; c < NO; c++)
                a += hs[j*(NH*NO) + head*NO + c] * att[head*NO + c];
            if (r < 4) d_as1[(n0+j)*NH + head] = a;
            else       d_ad1[(n0+j)*NH + head] = a;
        }
        return;
    }
    bb -= G1B;
    if (bb < XB2) {
        int sub = t >> 6, c = t & 63;
        int n = bb*4 + sub;
        if (c < NO) {
            float v;
            if      (c < 16) v = e0w[cat2[n*3+0]*16 + c];
            else if (c < 24) v = e1w[cat2[n*3+1]*8  + (c-16)];
            else if (c < 48) v = e2w[cat2[n*3+2]*24 + (c-24)];
            else             v = num2[n*3 + (c-48)];
            d_x2[n*NO + c] = v;
        }
        return;
    }
    bb -= XB2;
    if (bb < HB) {
        int i = bb*256 + t;
        if (i < E1N) atomicAdd(&d_cnt1[e1[E1N + i]], 1);
        else         atomicAdd(&d_cnt2[e2[E2N + (i - E1N)]], 1);
        return;
    }
    bb -= HB;
    if (bb == 0) {
        for (int idx = t; idx < NO*NO; idx += 256) {
            int i = idx / NO, j = idx % NO;
            float s = 0.f;
            #pragma unroll
            for (int k = 0; k < 64; k++) s += W[i*64+k] * W[j*64+k];
            d_M[idx] = 2.f * s;
        }
        return;
    }
    if (t < FUT*4) {
        int f = t >> 2, wd = t & 3;
        unsigned u = 0;
        for (int i = 0; i < 32; i++)
            if (A[(wd*32+i)*(PAST+FUT) + PAST + f]) u |= (1u << i);
        d_maskw[f*4 + wd] = u;
    }
}

// ================= Kernel B: warp-shuffle scan + z2 =================
template<int CHUNK, int NN>
__device__ __forceinline__ void scan_t(int* cnt, int* off, int* cur, int* wtot) {
    int t = threadIdx.x, lane = t & 31, wid = t >> 5;
    int start = t * CHUNK;
    int local[CHUNK];
    int s = 0;
    #pragma unroll
    for (int i = 0; i < CHUNK; i++) {
        local[i] = cnt[start+i] + 1;   // + self loop
        cnt[start+i] = 0;              // restore for next replay
        s += local[i];
    }
    int v = s;
    #pragma unroll
    for (int o = 1; o < 32; o <<= 1) {
        int u = __shfl_up_sync(0xffffffffu, v, o);
        if (lane >= o) v += u;
    }
    if (lane == 31) wtot[wid] = v;
    __syncthreads();
    if (wid == 0) {
        int x = wtot[lane];
        #pragma unroll
        for (int o = 1; o < 32; o <<= 1) {
            int u = __shfl_up_sync(0xffffffffu, x, o);
            if (lane >= o) x += u;
        }
        wtot[lane] = x;
    }
    __syncthreads();
    int run = v - s + (wid ? wtot[wid-1] : 0);
    #pragma unroll
    for (int i = 0; i < CHUNK; i++) {
        off[start+i] = run;
        cur[start+i] = run;
        run += local[i];
    }
    if (t == 1023) off[NN] = run;
}

__global__ void kScanZ2() {
    __shared__ float sm[NO*NO + Z2PB*NO];
    int b = blockIdx.x, t = threadIdx.x;
    if (b == 0) { scan_t<8, N1>(d_cnt1, d_off1, d_cur1, (int*)sm); return; }
    if (b == 1) { scan_t<4, N2>(d_cnt2, d_off2, d_cur2, (int*)sm); return; }
    int base = (b - 2) * Z2PB;
    float* Ms  = sm;
    float* x2s = sm + NO*NO;
    for (int idx = t; idx < NO*NO; idx += 1024) Ms[idx] = d_M[idx];
    for (int idx = t; idx < Z2PB*NO; idx += 1024) {
        int gl = base*NO + idx;
        x2s[idx] = (gl < N2*NO) ? d_x2[gl] : 0.f;
    }
    __syncthreads();
    if (t < Z2PB*NO) {
        int ln = t / NO, c = t % NO;
        int node = base + ln;
        if (node < N2) {
            float z = 0.f;
            #pragma unroll
            for (int j = 0; j < NO; j++) z += Ms[c*NO + j] * x2s[ln*NO + j];
            d_z2[node*NO + c] = z;
        }
    }
}

// ======== Kernel C: scatter (all entries incl. self loops) + g1 edge weights =====
__global__ void kScatter(const int* __restrict__ e1, const int* __restrict__ e2) {
    int i = blockIdx.x*256 + threadIdx.x;
    if (i < T1) {
        int s, d;
        if (i < E1N) { s = e1[i]; d = e1[E1N + i]; }
        else         { s = d = i - E1N; }
        int pos = atomicAdd(&d_cur1[d], 1);
        d_csr1[pos] = s;
        float4 as = *(const float4*)&d_as1[s*NH];
        float4 ad = *(const float4*)&d_ad1[d*NH];
        d_ew1[0*T1 + pos] = expf(lrelu(as.x + ad.x));
        d_ew1[1*T1 + pos] = expf(lrelu(as.y + ad.y));
        d_ew1[2*T1 + pos] = expf(lrelu(as.z + ad.z));
        d_ew1[3*T1 + pos] = expf(lrelu(as.w + ad.w));
    } else {
        int j = i - T1;
        if (j >= T2) return;
        int s, d;
        if (j < E2N) { s = e2[j]; d = e2[E2N + j]; }
        else         { s = d = j - E2N; }
        d_csr2[atomicAdd(&d_cur2[d], 1)] = s;
    }
}

// ============ Kernel D: GAT1 aggregate (precomputed weights) + quad ============
__global__ void kAgg1(const float* __restrict__ bias) {
    int n = blockIdx.x, t = threadIdx.x;
    int w = t >> 5, lane = t & 31;
    int beg = d_off1[n], end = d_off1[n+1];
    const float* ws = d_ew1 + w*T1;

    float ssum = 0.f, a0 = 0.f, a1 = 0.f, b0 = 0.f, b1 = 0.f;
    int c0 = lane, c1 = lane + 32;
    bool has1 = (c1 < NO);
    int i = beg;
    for (; i + 2 <= end; i += 2) {
        int s0 = d_csr1[i], s1 = d_csr1[i+1];
        float w0 = ws[i], w1 = ws[i+1];
        ssum += w0 + w1;
        const float* h0 = &d_h1[s0*(NH*NO) + w*NO];
        const float* h1 = &d_h1[s1*(NH*NO) + w*NO];
        a0 += w0 * h0[c0];
        b0 += w1 * h1[c0];
        if (has1) { a1 += w0 * h0[c1]; b1 += w1 * h1[c1]; }
    }
    if (i < end) {
        int s0 = d_csr1[i];
        float w0 = ws[i];
        ssum += w0;
        const float* h0 = &d_h1[s0*(NH*NO) + w*NO];
        a0 += w0 * h0[c0];
        if (has1) a1 += w0 * h0[c1];
    }
    a0 += b0; a1 += b1;
    float inv = 0.25f / (ssum + 1e-16f);

    __shared__ float so[NO];
    __shared__ float red[128];
    if (t < NO) so[t] = 0.f;
    __syncthreads();
    atomicAdd(&so[c0], a0 * inv);
    if (has1) atomicAdd(&so[c1], a1 * inv);
    __syncthreads();
    if (t < NO) {
        float v = so[t] + bias[t];
        so[t] = v;
        d_x1o[n*NO + t] = v;
    }
    __syncthreads();
    // quad: rows strided across warps, lanes over columns
    float p = 0.f;
    for (int r = w; r < NO; r += 4) {
        float xr = so[r];
        float acc = __ldg(&d_M[r*NO + c0]) * so[c0];
        if (has1) acc += __ldg(&d_M[r*NO + c1]) * so[c1];
        p += acc * xr;
    }
    red[t] = p;
    __syncthreads();
    if (t < 64) red[t] += red[t+64];
    __syncthreads();
    if (t < 32) {
        float v = red[t] + red[t+32];
        v = warp_sum(v);
        if (t == 0) d_q1h[n] = -0.5f * v;
    }
}

// ============ Kernel E: attention per (batch, f-quarter) + GAT2 linear ============
__global__ void kAttn(const float* __restrict__ lin,
                      const float* __restrict__ asrc, const float* __restrict__ adst) {
    int bi = blockIdx.x;
    int b = bi >> 2, q = bi & 3;
    int fbase = q * 16;
    int t = threadIdx.x;              // 256
    __shared__ float xt[PAST*51];     // x1 tile, padded stride 51
    __shared__ float zs[16*NO];
    __shared__ float x2s[16*NO];
    __shared__ float qh[PAST];
    __shared__ float yv[PAST];
    __shared__ float s_tmp[16];
    __shared__ unsigned msk[16*4];

    const float* x1src = d_x1o + (size_t)b*PAST*NO;
    for (int idx = t; idx < PAST*NO; idx += 256) {
        int p = idx / NO, c = idx % NO;
        xt[p*51 + c] = x1src[idx];
    }
    for (int idx = t; idx < 16*NO; idx += 256) {
        int fl = idx / NO, c = idx % NO;
        int n = b*FUT + fbase + fl;
        zs[idx]  = d_z2[n*NO + c];
        x2s[idx] = d_x2[n*NO + c];
    }
    if (t < PAST) { qh[t] = d_q1h[b*PAST + t]; yv[t] = d_y[b*PAST + t]; }
    if (t < 64)   msk[t] = d_maskw[(fbase + (t>>2))*4 + (t&3)];
    __syncthreads();

    int fl = t >> 4;       // 0..15
    int psub = t & 15;
    const float* zrow = zs + fl*NO;
    float sex = 0.f, swv = 0.f;
    #pragma unroll
    for (int k = 0; k < 8; k++) {
        int p = psub + k*16;
        const float* xr = xt + p*51;
        float dot = 0.f;
        #pragma unroll
        for (int c = 0; c < NO; c++) dot += zrow[c] * xr[c];
        float logit = qh[p] + dot;
        unsigned bit = (msk[fl*4 + (p>>5)] >> (p & 31)) & 1u;
        float ex = bit ? expf(logit) : 0.f;
        sex += ex;
        swv += ex * yv[p];
    }
    #pragma unroll
    for (int o = 8; o; o >>= 1) {
        sex += __shfl_xor_sync(0xffffffffu, sex, o);
        swv += __shfl_xor_sync(0xffffffffu, swv, o);
    }
    if (psub == 0) s_tmp[fl] = swv / (sex + 1e-16f);
    __syncthreads();

    if (t < 64) {
        int fl2 = t >> 2, h = t & 3;
        const float* xr = x2s + fl2*NO;
        float acc = 0.f;
        #pragma unroll 10
        for (int k = 0; k < NO; k++) acc += xr[k] * __ldg(&lin[k*NH + h]);
        int n = b*FUT + fbase + fl2;
        float v = acc + s_tmp[fl2] * __ldg(&lin[NO*NH + h]);
        d_h2[n*NH + h]  = v;
        d_as2[n*NH + h] = v * asrc[h];
        d_ad2[n*NH + h] = v * adst[h];
    }
}

// ================= Kernel F: GAT2 aggregate =================
__global__ void kAgg2(const float* __restrict__ bias, float* __restrict__ out) {
    int n = blockIdx.x*4 + (threadIdx.x >> 5);
    int lane = threadIdx.x & 31;
    int beg = d_off2[n], end = d_off2[n+1];
    float4 ad = *(const float4*)&d_ad2[n*NH];
    float ss0=0,ss1=0,ss2=0,ss3=0, ws0=0,ws1=0,ws2=0,ws3=0;
    for (int i = beg + lane; i < end; i += 32) {
        int s = d_csr2[i];
        float4 av = *(const float4*)&d_as2[s*NH];
        float4 hv = *(const float4*)&d_h2[s*NH];
        float e0 = expf(lrelu(av.x + ad.x));
        float e1 = expf(lrelu(av.y + ad.y));
        float e2 = expf(lrelu(av.z + ad.z));
        float e3 = expf(lrelu(av.w + ad.w));
        ss0+=e0; ws0+=e0*hv.x;
        ss1+=e1; ws1+=e1*hv.y;
        ss2+=e2; ws2+=e2*hv.z;
        ss3+=e3; ws3+=e3*hv.w;
    }
    ss0=warp_sum(ss0); ws0=warp_sum(ws0);
    ss1=warp_sum(ss1); ws1=warp_sum(ws1);
    ss2=warp_sum(ss2); ws2=warp_sum(ws2);
    ss3=warp_sum(ss3); ws3=warp_sum(ws3);
    if (lane == 0) {
        float total = 0.25f*ws0/(ss0+1e-16f) + 0.25f*ws1/(ss1+1e-16f)
                    + 0.25f*ws2/(ss2+1e-16f) + 0.25f*ws3/(ss3+1e-16f);
        out[n] = total + bias[0];
    }
}

// ================= launch =================
extern "C" void kernel_launch(void* const* d_in, const int* in_sizes, int n_in,
                              void* d_out, int out_size) {
    const int*   cat1   = (const int*)  d_in[0];
    const float* num1   = (const float*)d_in[1];
    const int*   cat2   = (const int*)  d_in[2];
    const float* num2   = (const float*)d_in[3];
    const int*   e1     = (const int*)  d_in[4];
    const int*   e2     = (const int*)  d_in[5];
    const int*   A      = (const int*)  d_in[6];
    const float* emb0   = (const float*)d_in[7];
    const float* emb1   = (const float*)d_in[8];
    const float* emb2   = (const float*)d_in[9];
    const float* g1_lin = (const float*)d_in[10];
    const float* g1_as  = (const float*)d_in[11];
    const float* g1_ad  = (const float*)d_in[12];
    const float* g1_b   = (const float*)d_in[13];
    const float* g2_lin = (const float*)d_in[14];
    const float* g2_as  = (const float*)d_in[15];
    const float* g2_ad  = (const float*)d_in[16];
    const float* g2_b   = (const float*)d_in[17];
    const float* W      = (const float*)d_in[18];
    float* out = (float*)d_out;

    kA<<<G1B + XB2 + HB + 2, 256>>>(cat1, num1, cat2, num2, e1, e2, A,
                                    emb0, emb1, emb2, g1_lin, g1_as, g1_ad, W);
    kScanZ2<<<2 + Z2B, 1024>>>();
    kScatter<<<SCB, 256>>>(e1, e2);
    kAgg1<<<N1, 128>>>(g1_b);
    kAttn<<<BN*4, 256>>>(g2_lin, g2_as, g2_ad);
    kAgg2<<<N2/4, 128>>>(g2_b, out);
}

// round 5
// speedup vs baseline: 1.5011x; 1.0789x over previous
#include <cuda_runtime.h>
#include <math.h>

#define BN   64
#define PAST 128
#define FUT  64
#define NF   51
#define NO   50
#define NH   4
#define N1   (BN*PAST)   /* 8192 */
#define N2   (BN*FUT)    /* 4096 */
#define E1N  (N1*16)
#define E2N  (N2*16)
#define T1   (E1N+N1)    /* 139264 */
#define T2   (E2N+N2)    /* 69632 */
#define G1B  (N1/16)             /* 512 */
#define XB2  (N2/4)              /* 1024 */
#define HB   ((E1N+E2N)/256)     /* 768 */
#define Z2PB 20
#define Z2B  ((N2+Z2PB-1)/Z2PB)  /* 205 */
#define SCB  ((T1+T2+255)/256)   /* 816 */

// ---------------- scratch ----------------
__device__ float d_y  [N1];
__device__ float d_x2 [N2*NO];
__device__ float d_h1 [N1*NH*NO];
__device__ __align__(16) float d_as1[N1*NH];
__device__ __align__(16) float d_ad1[N1*NH];
__device__ float d_x1o[N1*NO];
__device__ float d_M  [NO*NO];
__device__ float d_q1h[N1];
__device__ float d_z2 [N2*NO];
__device__ __align__(16) float d_h2 [N2*NH];
__device__ __align__(16) float d_as2[N2*NH];
__device__ __align__(16) float d_ad2[N2*NH];
__device__ float4 d_ew4[T1];           // interleaved per-edge head weights
__device__ unsigned d_maskw[FUT*4];
__device__ int   d_cnt1[N1];
__device__ int   d_off1[N1+1];
__device__ int   d_cur1[N1];
__device__ int   d_csr1[T1];
__device__ int   d_cnt2[N2];
__device__ int   d_off2[N2+1];
__device__ int   d_cur2[N2];
__device__ int   d_csr2[T2];

__device__ __forceinline__ float warp_sum(float v) {
    #pragma unroll
    for (int o = 16; o; o >>= 1) v += __shfl_xor_sync(0xffffffffu, v, o);
    return v;
}
__device__ __forceinline__ float lrelu(float x) { return x > 0.f ? x : 0.2f * x; }

// ================= kGemm: GAT1 linear, 16 nodes/block =================
__global__ void kGemm(const int* __restrict__ cat1, const float* __restrict__ num1,
                      const float* __restrict__ e0w, const float* __restrict__ e1w,
                      const float* __restrict__ e2w,
                      const float* __restrict__ lin, const float* __restrict__ asrc,
                      const float* __restrict__ adst) {
    __shared__ float xs[16*NF];
    __shared__ float hs[16*NH*NO];
    int t = threadIdx.x;
    int n0 = blockIdx.x*16;
    for (int idx = t; idx < 16*NF; idx += 256) {
        int j = idx / NF, k = idx % NF, n = n0 + j;
        float v;
        if      (k < 16) v = e0w[cat1[n*3+0]*16 + k];
        else if (k < 24) v = e1w[cat1[n*3+1]*8  + (k-16)];
        else if (k < 48) v = e2w[cat1[n*3+2]*24 + (k-24)];
        else             v = num1[n*3 + (k-48)];
        xs[idx] = v;
        if (k == NF-1) d_y[n] = v;
    }
    __syncthreads();
    if (t < NH*NO) {
        float acc[16];
        #pragma unroll
        for (int j = 0; j < 16; j++) acc[j] = 0.f;
        for (int k = 0; k < NF; k++) {
            float l = __ldg(&lin[k*(NH*NO) + t]);
            #pragma unroll
            for (int j = 0; j < 16; j++) acc[j] += xs[j*NF + k] * l;
        }
        #pragma unroll
        for (int j = 0; j < 16; j++) {
            d_h1[(n0+j)*(NH*NO) + t] = acc[j];
            hs[j*(NH*NO) + t] = acc[j];
        }
    }
    __syncthreads();
    if (t < 128) {
        int j = t >> 3, r = t & 7, head = r & 3;
        const float* att = (r < 4) ? asrc : adst;
        float a = 0.f;
        #pragma unroll
        for (int c = 0; c < NO; c++)
            a += hs[j*(NH*NO) + head*NO + c] * att[head*NO + c];
        if (r < 4) d_as1[(n0+j)*NH + head] = a;
        else       d_ad1[(n0+j)*NH + head] = a;
    }
}

// ================= kHist =================
__global__ void kHist(const int* __restrict__ e1, const int* __restrict__ e2) {
    int i = blockIdx.x*256 + threadIdx.x;
    if (i < E1N) atomicAdd(&d_cnt1[e1[E1N + i]], 1);
    else         atomicAdd(&d_cnt2[e2[E2N + (i - E1N)]], 1);
}

// ================= kPre2: x2 pre | M | mask =================
__global__ void kPre2(const int* __restrict__ cat2, const float* __restrict__ num2,
                      const int* __restrict__ A,
                      const float* __restrict__ e0w, const float* __restrict__ e1w,
                      const float* __restrict__ e2w, const float* __restrict__ W) {
    int bb = blockIdx.x, t = threadIdx.x;
    if (bb < XB2) {
        int sub = t >> 6, c = t & 63;
        int n = bb*4 + sub;
        if (c < NO) {
            float v;
            if      (c < 16) v = e0w[cat2[n*3+0]*16 + c];
            else if (c < 24) v = e1w[cat2[n*3+1]*8  + (c-16)];
            else if (c < 48) v = e2w[cat2[n*3+2]*24 + (c-24)];
            else             v = num2[n*3 + (c-48)];
            d_x2[n*NO + c] = v;
        }
        return;
    }
    if (bb == XB2) {
        for (int idx = t; idx < NO*NO; idx += 256) {
            int i = idx / NO, j = idx % NO;
            float s = 0.f;
            #pragma unroll
            for (int k = 0; k < 64; k++) s += W[i*64+k] * W[j*64+k];
            d_M[idx] = 2.f * s;
        }
        return;
    }
    if (t < FUT*4) {
        int f = t >> 2, wd = t & 3;
        unsigned u = 0;
        for (int i = 0; i < 32; i++)
            if (A[(wd*32+i)*(PAST+FUT) + PAST + f]) u |= (1u << i);
        d_maskw[f*4 + wd] = u;
    }
}

// ================= kZ2 =================
__global__ void kZ2() {
    __shared__ float sm[NO*NO + Z2PB*NO];
    int t = threadIdx.x;
    int base = blockIdx.x * Z2PB;
    float* Ms  = sm;
    float* x2s = sm + NO*NO;
    for (int idx = t; idx < NO*NO; idx += 1024) Ms[idx] = d_M[idx];
    for (int idx = t; idx < Z2PB*NO; idx += 1024) {
        int gl = base*NO + idx;
        x2s[idx] = (gl < N2*NO) ? d_x2[gl] : 0.f;
    }
    __syncthreads();
    if (t < Z2PB*NO) {
        int ln = t / NO, c = t % NO;
        int node = base + ln;
        if (node < N2) {
            float z = 0.f;
            #pragma unroll
            for (int j = 0; j < NO; j++) z += Ms[c*NO + j] * x2s[ln*NO + j];
            d_z2[node*NO + c] = z;
        }
    }
}

// ================= kScan: warp-shuffle scan, 2 blocks =================
template<int CHUNK, int NN>
__device__ __forceinline__ void scan_t(int* cnt, int* off, int* cur, int* wtot) {
    int t = threadIdx.x, lane = t & 31, wid = t >> 5;
    int start = t * CHUNK;
    int local[CHUNK];
    int s = 0;
    #pragma unroll
    for (int i = 0; i < CHUNK; i++) {
        local[i] = cnt[start+i] + 1;   // + self loop
        cnt[start+i] = 0;              // restore for next replay
        s += local[i];
    }
    int v = s;
    #pragma unroll
    for (int o = 1; o < 32; o <<= 1) {
        int u = __shfl_up_sync(0xffffffffu, v, o);
        if (lane >= o) v += u;
    }
    if (lane == 31) wtot[wid] = v;
    __syncthreads();
    if (wid == 0) {
        int x = wtot[lane];
        #pragma unroll
        for (int o = 1; o < 32; o <<= 1) {
            int u = __shfl_up_sync(0xffffffffu, x, o);
            if (lane >= o) x += u;
        }
        wtot[lane] = x;
    }
    __syncthreads();
    int run = v - s + (wid ? wtot[wid-1] : 0);
    #pragma unroll
    for (int i = 0; i < CHUNK; i++) {
        off[start+i] = run;
        cur[start+i] = run;
        run += local[i];
    }
    if (t == 1023) off[NN] = run;
}
__global__ void kScan() {
    __shared__ int wtot[32];
    if (blockIdx.x == 0) scan_t<8, N1>(d_cnt1, d_off1, d_cur1, wtot);
    else                 scan_t<4, N2>(d_cnt2, d_off2, d_cur2, wtot);
}

// ================= kScatter: CSR fill + interleaved g1 edge weights =================
__global__ void kScatter(const int* __restrict__ e1, const int* __restrict__ e2) {
    int i = blockIdx.x*256 + threadIdx.x;
    if (i < T1) {
        int s, d;
        if (i < E1N) { s = e1[i]; d = e1[E1N + i]; }
        else         { s = d = i - E1N; }
        int pos = atomicAdd(&d_cur1[d], 1);
        d_csr1[pos] = s;
        float4 as = *(const float4*)&d_as1[s*NH];
        float4 ad = *(const float4*)&d_ad1[d*NH];
        float4 w;
        w.x = expf(lrelu(as.x + ad.x));
        w.y = expf(lrelu(as.y + ad.y));
        w.z = expf(lrelu(as.z + ad.z));
        w.w = expf(lrelu(as.w + ad.w));
        d_ew4[pos] = w;
    } else {
        int j = i - T1;
        if (j >= T2) return;
        int s, d;
        if (j < E2N) { s = e2[j]; d = e2[E2N + j]; }
        else         { s = d = j - E2N; }
        d_csr2[atomicAdd(&d_cur2[d], 1)] = s;
    }
}

// ============ kAgg1: GAT1 aggregate + quad, 2 nodes per 256-thread block ============
__global__ void kAgg1(const float* __restrict__ bias) {
    int t = threadIdx.x;
    int half = t >> 7, lt = t & 127;
    int n = blockIdx.x*2 + half;
    int w = lt >> 5, lane = lt & 31;
    int beg = d_off1[n], end = d_off1[n+1];
    const float* ws = (const float*)d_ew4 + w;

    float ssum = 0.f, a0 = 0.f, a1 = 0.f, b0 = 0.f, b1 = 0.f;
    int c0 = lane, c1 = lane + 32;
    bool has1 = (c1 < NO);
    int i = beg;
    for (; i + 2 <= end; i += 2) {
        int s0 = d_csr1[i], s1 = d_csr1[i+1];
        float w0 = ws[4*i], w1 = ws[4*(i+1)];
        ssum += w0 + w1;
        const float* h0 = &d_h1[s0*(NH*NO) + w*NO];
        const float* h1 = &d_h1[s1*(NH*NO) + w*NO];
        a0 += w0 * h0[c0];
        b0 += w1 * h1[c0];
        if (has1) { a1 += w0 * h0[c1]; b1 += w1 * h1[c1]; }
    }
    if (i < end) {
        int s0 = d_csr1[i];
        float w0 = ws[4*i];
        ssum += w0;
        const float* h0 = &d_h1[s0*(NH*NO) + w*NO];
        a0 += w0 * h0[c0];
        if (has1) a1 += w0 * h0[c1];
    }
    a0 += b0; a1 += b1;
    float inv = 0.25f / (ssum + 1e-16f);

    __shared__ float so[2][NO];
    __shared__ float red[256];
    if (lt < NO) so[half][lt] = 0.f;
    __syncthreads();
    atomicAdd(&so[half][c0], a0 * inv);
    if (has1) atomicAdd(&so[half][c1], a1 * inv);
    __syncthreads();
    if (lt < NO) {
        float v = so[half][lt] + bias[lt];
        so[half][lt] = v;
        d_x1o[n*NO + lt] = v;
    }
    __syncthreads();
    float p = 0.f;
    for (int r = w; r < NO; r += 4) {
        float xr = so[half][r];
        float acc = __ldg(&d_M[r*NO + c0]) * so[half][c0];
        if (has1) acc += __ldg(&d_M[r*NO + c1]) * so[half][c1];
        p += acc * xr;
    }
    red[t] = p;
    __syncthreads();
    if (lt < 64) red[t] += red[t+64];
    __syncthreads();
    if (lt < 32) {
        float v = red[t] + red[t+32];
        v = warp_sum(v);
        if (lane == 0) d_q1h[n] = -0.5f * v;
    }
}

// ============ kAttn: attention per (batch, f-quarter) + GAT2 linear ============
__global__ void kAttn(const float* __restrict__ lin,
                      const float* __restrict__ asrc, const float* __restrict__ adst) {
    int bi = blockIdx.x;
    int b = bi >> 2, q = bi & 3;
    int fbase = q * 16;
    int t = threadIdx.x;
    __shared__ float xt[PAST*51];
    __shared__ float zs[16*NO];
    __shared__ float x2s[16*NO];
    __shared__ float qh[PAST];
    __shared__ float yv[PAST];
    __shared__ float s_tmp[16];
    __shared__ unsigned msk[16*4];

    const float* x1src = d_x1o + (size_t)b*PAST*NO;
    for (int idx = t; idx < PAST*NO; idx += 256) {
        int p = idx / NO, c = idx % NO;
        xt[p*51 + c] = x1src[idx];
    }
    for (int idx = t; idx < 16*NO; idx += 256) {
        int fl = idx / NO, c = idx % NO;
        int n = b*FUT + fbase + fl;
        zs[idx]  = d_z2[n*NO + c];
        x2s[idx] = d_x2[n*NO + c];
    }
    if (t < PAST) { qh[t] = d_q1h[b*PAST + t]; yv[t] = d_y[b*PAST + t]; }
    if (t < 64)   msk[t] = d_maskw[(fbase + (t>>2))*4 + (t&3)];
    __syncthreads();

    int fl = t >> 4;
    int psub = t & 15;
    const float* zrow = zs + fl*NO;
    float sex = 0.f, swv = 0.f;
    #pragma unroll
    for (int k = 0; k < 8; k++) {
        int p = psub + k*16;
        const float* xr = xt + p*51;
        float dot = 0.f;
        #pragma unroll
        for (int c = 0; c < NO; c++) dot += zrow[c] * xr[c];
        float logit = qh[p] + dot;
        unsigned bit = (msk[fl*4 + (p>>5)] >> (p & 31)) & 1u;
        float ex = bit ? expf(logit) : 0.f;
        sex += ex;
        swv += ex * yv[p];
    }
    #pragma unroll
    for (int o = 8; o; o >>= 1) {
        sex += __shfl_xor_sync(0xffffffffu, sex, o);
        swv += __shfl_xor_sync(0xffffffffu, swv, o);
    }
    if (psub == 0) s_tmp[fl] = swv / (sex + 1e-16f);
    __syncthreads();

    if (t < 64) {
        int fl2 = t >> 2, h = t & 3;
        const float* xr = x2s + fl2*NO;
        float acc = 0.f;
        #pragma unroll 10
        for (int k = 0; k < NO; k++) acc += xr[k] * __ldg(&lin[k*NH + h]);
        int n = b*FUT + fbase + fl2;
        float v = acc + s_tmp[fl2] * __ldg(&lin[NO*NH + h]);
        d_h2[n*NH + h]  = v;
        d_as2[n*NH + h] = v * asrc[h];
        d_ad2[n*NH + h] = v * adst[h];
    }
}

// ================= kAgg2 =================
__global__ void kAgg2(const float* __restrict__ bias, float* __restrict__ out) {
    int n = blockIdx.x*4 + (threadIdx.x >> 5);
    int lane = threadIdx.x & 31;
    int beg = d_off2[n], end = d_off2[n+1];
    float4 ad = *(const float4*)&d_ad2[n*NH];
    float ss0=0,ss1=0,ss2=0,ss3=0, ws0=0,ws1=0,ws2=0,ws3=0;
    for (int i = beg + lane; i < end; i += 32) {
        int s = d_csr2[i];
        float4 av = *(const float4*)&d_as2[s*NH];
        float4 hv = *(const float4*)&d_h2[s*NH];
        float e0 = expf(lrelu(av.x + ad.x));
        float e1 = expf(lrelu(av.y + ad.y));
        float e2 = expf(lrelu(av.z + ad.z));
        float e3 = expf(lrelu(av.w + ad.w));
        ss0+=e0; ws0+=e0*hv.x;
        ss1+=e1; ws1+=e1*hv.y;
        ss2+=e2; ws2+=e2*hv.z;
        ss3+=e3; ws3+=e3*hv.w;
    }
    ss0=warp_sum(ss0); ws0=warp_sum(ws0);
    ss1=warp_sum(ss1); ws1=warp_sum(ws1);
    ss2=warp_sum(ss2); ws2=warp_sum(ws2);
    ss3=warp_sum(ss3); ws3=warp_sum(ws3);
    if (lane == 0) {
        float total = 0.25f*ws0/(ss0+1e-16f) + 0.25f*ws1/(ss1+1e-16f)
                    + 0.25f*ws2/(ss2+1e-16f) + 0.25f*ws3/(ss3+1e-16f);
        out[n] = total + bias[0];
    }
}

// ================= launch (multi-stream fork/join, graph-capturable) =================
extern "C" void kernel_launch(void* const* d_in, const int* in_sizes, int n_in,
                              void* d_out, int out_size) {
    const int*   cat1   = (const int*)  d_in[0];
    const float* num1   = (const float*)d_in[1];
    const int*   cat2   = (const int*)  d_in[2];
    const float* num2   = (const float*)d_in[3];
    const int*   e1     = (const int*)  d_in[4];
    const int*   e2     = (const int*)  d_in[5];
    const int*   A      = (const int*)  d_in[6];
    const float* emb0   = (const float*)d_in[7];
    const float* emb1   = (const float*)d_in[8];
    const float* emb2   = (const float*)d_in[9];
    const float* g1_lin = (const float*)d_in[10];
    const float* g1_as  = (const float*)d_in[11];
    const float* g1_ad  = (const float*)d_in[12];
    const float* g1_b   = (const float*)d_in[13];
    const float* g2_lin = (const float*)d_in[14];
    const float* g2_as  = (const float*)d_in[15];
    const float* g2_ad  = (const float*)d_in[16];
    const float* g2_b   = (const float*)d_in[17];
    const float* W      = (const float*)d_in[18];
    float* out = (float*)d_out;

    // one-time resource init (first call is the uncaptured correctness run)
    static cudaStream_t s1 = nullptr, s2 = nullptr;
    static cudaEvent_t evF = nullptr, evScan = nullptr, evS2 = nullptr;
    if (!s1) {
        cudaStreamCreateWithFlags(&s1, cudaStreamNonBlocking);
        cudaStreamCreateWithFlags(&s2, cudaStreamNonBlocking);
        cudaEventCreateWithFlags(&evF,    cudaEventDisableTiming);
        cudaEventCreateWithFlags(&evScan, cudaEventDisableTiming);
        cudaEventCreateWithFlags(&evS2,   cudaEventDisableTiming);
    }

    // fork
    cudaEventRecord(evF, 0);
    cudaStreamWaitEvent(s1, evF, 0);
    cudaStreamWaitEvent(s2, evF, 0);

    // chain s1: hist -> scan
    kHist<<<HB, 256, 0, s1>>>(e1, e2);
    kScan<<<2, 1024, 0, s1>>>();
    cudaEventRecord(evScan, s1);

    // chain s2: x2 pre / M / mask -> z2
    kPre2<<<XB2 + 2, 256, 0, s2>>>(cat2, num2, A, emb0, emb1, emb2, W);
    kZ2<<<Z2B, 1024, 0, s2>>>();
    cudaEventRecord(evS2, s2);

    // main chain: gemm overlaps s1/s2
    kGemm<<<G1B, 256>>>(cat1, num1, emb0, emb1, emb2, g1_lin, g1_as, g1_ad);
    cudaStreamWaitEvent(0, evScan, 0);
    kScatter<<<SCB, 256>>>(e1, e2);
    cudaStreamWaitEvent(0, evS2, 0);
    kAgg1<<<N1/2, 256>>>(g1_b);
    kAttn<<<BN*4, 256>>>(g2_lin, g2_as, g2_ad);
    kAgg2<<<N2/4, 128>>>(g2_b, out);
}